// round 4
// baseline (speedup 1.0000x reference)
#include <cuda_runtime.h>
#include <cuda_fp16.h>
#include <cstdint>

#define NNODES 100000
#define NEDGES 1600000
#define NB     391            // ceil(NNODES/256)
#define NF4    (NNODES * 16)  // float4 slots per fp32 plane

// ---------------------------------------------------------------------------
// Device-global scratch (no allocation allowed).
__device__ __half2 g_feat[4][NNODES * 32];   // planes 0..3 fp16, 12.8 MB each
__device__ int2    g_csr[NEDGES];            // {src, bits(dis[src])} sorted by dst
__device__ int     g_off[NNODES + 1];
__device__ int     g_cursor[NNODES];
__device__ int     g_deg[NNODES];
__device__ float   g_dis[NNODES];
__device__ int     g_blocksum[512];
__device__ int     g_blockoff[512];
__device__ int     g_idx64;

// ---------------------------------------------------------------------------
__global__ void detect_idx_kernel(const int* __restrict__ ei32) {
    int lane = threadIdx.x;
    int nz = 0;
    for (int i = lane; i < 2048; i += 32) nz |= ei32[2 * i + 1];
    unsigned m = __ballot_sync(0xffffffffu, nz != 0);
    if (lane == 0) g_idx64 = (m == 0) ? 1 : 0;
}

__global__ void zerodeg_kernel() {
    int i = blockIdx.x * blockDim.x + threadIdx.x;
    if (i < NNODES) g_deg[i] = 0;
}

__global__ void deg_kernel(const void* __restrict__ eiv) {
    int e = blockIdx.x * blockDim.x + threadIdx.x;
    if (e >= NEDGES) return;
    int d;
    if (g_idx64) d = (int)((const long long*)eiv)[NEDGES + e];
    else         d = ((const int*)eiv)[NEDGES + e];
    atomicAdd(&g_deg[d], 1);
}

// ---------------------------------------------------------------------------
// 3-kernel exclusive scan of g_deg -> g_off / g_cursor
__global__ void partial_kernel() {
    __shared__ int s[256];
    int i = blockIdx.x * 256 + threadIdx.x;
    int v = (i < NNODES) ? g_deg[i] : 0;
    s[threadIdx.x] = v; __syncthreads();
    for (int st = 128; st > 0; st >>= 1) {
        if (threadIdx.x < st) s[threadIdx.x] += s[threadIdx.x + st];
        __syncthreads();
    }
    if (threadIdx.x == 0) g_blocksum[blockIdx.x] = s[0];
}

__global__ void scanblock_kernel() {
    __shared__ int s[512];
    int t = threadIdx.x;
    int v = (t < NB) ? g_blocksum[t] : 0;
    s[t] = v; __syncthreads();
    for (int st = 1; st < 512; st <<= 1) {
        int add = (t >= st) ? s[t - st] : 0;
        __syncthreads();
        s[t] += add;
        __syncthreads();
    }
    if (t < NB) g_blockoff[t] = s[t] - v;   // exclusive
}

__global__ void offsets_kernel() {
    __shared__ int s[256];
    int i = blockIdx.x * 256 + threadIdx.x;
    int v = (i < NNODES) ? g_deg[i] : 0;
    s[threadIdx.x] = v; __syncthreads();
    for (int st = 1; st < 256; st <<= 1) {
        int add = (threadIdx.x >= st) ? s[threadIdx.x - st] : 0;
        __syncthreads();
        s[threadIdx.x] += add;
        __syncthreads();
    }
    int off = g_blockoff[blockIdx.x] + s[threadIdx.x] - v;  // exclusive
    if (i < NNODES) { g_off[i] = off; g_cursor[i] = off; }
    if (i == NNODES - 1) g_off[NNODES] = off + v;
}

__global__ void dis_kernel() {
    int i = blockIdx.x * blockDim.x + threadIdx.x;
    if (i >= NNODES) return;
    g_dis[i] = rsqrtf(fmaxf((float)g_deg[i], 1.0f));
}

// fill CSR: pos = cursor[dst]++ ; csr[pos] = {src, bits(dis[src])}
__global__ void fill_kernel(const void* __restrict__ eiv) {
    int e = blockIdx.x * blockDim.x + threadIdx.x;
    if (e >= NEDGES) return;
    int s, d;
    if (g_idx64) {
        const long long* p = (const long long*)eiv;
        s = (int)p[e]; d = (int)p[NEDGES + e];
    } else {
        const int* p = (const int*)eiv;
        s = p[e]; d = p[NEDGES + e];
    }
    int pos = atomicAdd(&g_cursor[d], 1);
    g_csr[pos] = make_int2(s, __float_as_int(g_dis[s]));
}

// ---------------------------------------------------------------------------
__global__ void init_kernel(const float4* __restrict__ x4) {
    int i = blockIdx.x * blockDim.x + threadIdx.x;
    if (i >= NF4) return;
    float4 v = x4[i];
    g_feat[0][2 * i]     = __floats2half2_rn(v.x, v.y);
    g_feat[0][2 * i + 1] = __floats2half2_rn(v.z, v.w);
}

// ---------------------------------------------------------------------------
// Warp-per-node pull gather: lane owns 2 halves (4 B) of the 128 B fp16 row.
// Edge records read as uniform-address broadcast loads; fp32 accumulation.
__device__ __forceinline__ float2 gather_accum(int node, int lane,
                                               const unsigned* __restrict__ fp) {
    int beg = g_off[node], end = g_off[node + 1];
    float2 a0 = {0.f, 0.f}, a1 = {0.f, 0.f}, a2 = {0.f, 0.f}, a3 = {0.f, 0.f};

    int j = beg;
    for (; j + 4 <= end; j += 4) {
        int2 e0 = __ldg(&g_csr[j]);
        int2 e1 = __ldg(&g_csr[j + 1]);
        int2 e2 = __ldg(&g_csr[j + 2]);
        int2 e3 = __ldg(&g_csr[j + 3]);
        unsigned r0 = __ldg(&fp[e0.x * 32 + lane]);
        unsigned r1 = __ldg(&fp[e1.x * 32 + lane]);
        unsigned r2 = __ldg(&fp[e2.x * 32 + lane]);
        unsigned r3 = __ldg(&fp[e3.x * 32 + lane]);
        float2 f0 = __half22float2(*reinterpret_cast<__half2*>(&r0));
        float2 f1 = __half22float2(*reinterpret_cast<__half2*>(&r1));
        float2 f2 = __half22float2(*reinterpret_cast<__half2*>(&r2));
        float2 f3 = __half22float2(*reinterpret_cast<__half2*>(&r3));
        float w0 = __int_as_float(e0.y), w1 = __int_as_float(e1.y);
        float w2 = __int_as_float(e2.y), w3 = __int_as_float(e3.y);
        a0.x = fmaf(w0, f0.x, a0.x); a0.y = fmaf(w0, f0.y, a0.y);
        a1.x = fmaf(w1, f1.x, a1.x); a1.y = fmaf(w1, f1.y, a1.y);
        a2.x = fmaf(w2, f2.x, a2.x); a2.y = fmaf(w2, f2.y, a2.y);
        a3.x = fmaf(w3, f3.x, a3.x); a3.y = fmaf(w3, f3.y, a3.y);
    }
    for (; j < end; j++) {
        int2 e0 = __ldg(&g_csr[j]);
        unsigned r0 = __ldg(&fp[e0.x * 32 + lane]);
        float2 f0 = __half22float2(*reinterpret_cast<__half2*>(&r0));
        float w0 = __int_as_float(e0.y);
        a0.x = fmaf(w0, f0.x, a0.x); a0.y = fmaf(w0, f0.y, a0.y);
    }
    a0.x = (a0.x + a1.x) + (a2.x + a3.x);
    a0.y = (a0.y + a1.y) + (a2.y + a3.y);
    return a0;
}

// iterations k = 1..3: feat_k = feat_{k-1} - dis*agg  (fp16 store)
__global__ void gather_kernel(int k) {
    int t = blockIdx.x * blockDim.x + threadIdx.x;
    int node = t >> 5;
    if (node >= NNODES) return;
    int lane = t & 31;

    const unsigned* fp = reinterpret_cast<const unsigned*>(g_feat[k - 1]);
    unsigned*       fn = reinterpret_cast<unsigned*>(g_feat[k]);

    float2 a = gather_accum(node, lane, fp);

    float disn = g_dis[node];
    unsigned own = fp[node * 32 + lane];
    float2 f = __half22float2(*reinterpret_cast<__half2*>(&own));
    __half2 o = __floats2half2_rn(f.x - disn * a.x, f.y - disn * a.y);
    fn[node * 32 + lane] = *reinterpret_cast<unsigned*>(&o);
}

// iteration k = 4 fused with the polynomial combine:
// out = 0.6*x - 0.4*f1 + 0.3*f2 - 0.2*f3 + 0.1*(f3 - dis*agg)
__global__ void gather_final_kernel(const float2* __restrict__ x2,
                                    float2* __restrict__ out2) {
    int t = blockIdx.x * blockDim.x + threadIdx.x;
    int node = t >> 5;
    if (node >= NNODES) return;
    int lane = t & 31;

    const unsigned* fp3 = reinterpret_cast<const unsigned*>(g_feat[3]);

    float2 a = gather_accum(node, lane, fp3);

    float disn = g_dis[node];
    int ri = node * 32 + lane;

    unsigned o3 = fp3[ri];
    float2 f3 = __half22float2(*reinterpret_cast<__half2*>(&o3));
    float2 f4;
    f4.x = f3.x - disn * a.x;
    f4.y = f3.y - disn * a.y;

    unsigned o1 = reinterpret_cast<const unsigned*>(g_feat[1])[ri];
    unsigned o2w = reinterpret_cast<const unsigned*>(g_feat[2])[ri];
    float2 f1 = __half22float2(*reinterpret_cast<__half2*>(&o1));
    float2 f2 = __half22float2(*reinterpret_cast<__half2*>(&o2w));
    float2 xv = __ldg(&x2[ri]);

    float2 o;
    o.x = fmaf(0.1f, f4.x, fmaf(-0.2f, f3.x, fmaf(0.3f, f2.x, fmaf(-0.4f, f1.x, 0.6f * xv.x))));
    o.y = fmaf(0.1f, f4.y, fmaf(-0.2f, f3.y, fmaf(0.3f, f2.y, fmaf(-0.4f, f1.y, 0.6f * xv.y))));
    out2[ri] = o;
}

// ---------------------------------------------------------------------------
extern "C" void kernel_launch(void* const* d_in, const int* in_sizes, int n_in,
                              void* d_out, int out_size) {
    const float4* x4 = (const float4*)d_in[0];
    const void*   ei = d_in[1];

    detect_idx_kernel<<<1, 32>>>((const int*)ei);
    zerodeg_kernel<<<NB, 256>>>();
    deg_kernel<<<(NEDGES + 255) / 256, 256>>>(ei);
    partial_kernel<<<NB, 256>>>();
    scanblock_kernel<<<1, 512>>>();
    offsets_kernel<<<NB, 256>>>();
    dis_kernel<<<NB, 256>>>();
    fill_kernel<<<(NEDGES + 255) / 256, 256>>>(ei);
    init_kernel<<<(NF4 + 255) / 256, 256>>>(x4);

    const int gthreads = NNODES * 32;
    const int gblocks = (gthreads + 255) / 256;
    for (int k = 1; k <= 3; k++)
        gather_kernel<<<gblocks, 256>>>(k);
    gather_final_kernel<<<gblocks, 256>>>((const float2*)d_in[0], (float2*)d_out);
}

// round 5
// speedup vs baseline: 1.0538x; 1.0538x over previous
#include <cuda_runtime.h>
#include <cuda_fp16.h>
#include <cstdint>

#define NNODES 100000
#define NEDGES 1600000
#define NB     391            // ceil(NNODES/256)
#define NF4    (NNODES * 16)  // float4 slots per fp32 plane

// ---------------------------------------------------------------------------
// Device-global scratch (no allocation allowed).
__device__ __half2 g_feat[4][NNODES * 32];   // planes 0..3 fp16, 12.8 MB each
__device__ int2    g_csr[NEDGES];            // {src, bits(dis[src])} sorted by dst
__device__ int     g_off[NNODES + 1];
__device__ int     g_cursor[NNODES];
__device__ int     g_deg[NNODES];
__device__ float   g_dis[NNODES];
__device__ int     g_blocksum[512];
__device__ int     g_blockoff[512];
__device__ int     g_idx64;

// ---------------------------------------------------------------------------
__global__ void detect_idx_kernel(const int* __restrict__ ei32) {
    int lane = threadIdx.x;
    int nz = 0;
    for (int i = lane; i < 2048; i += 32) nz |= ei32[2 * i + 1];
    unsigned m = __ballot_sync(0xffffffffu, nz != 0);
    if (lane == 0) g_idx64 = (m == 0) ? 1 : 0;
}

__global__ void zerodeg_kernel() {
    int i = blockIdx.x * blockDim.x + threadIdx.x;
    if (i < NNODES) g_deg[i] = 0;
}

__global__ void deg_kernel(const void* __restrict__ eiv) {
    int e = blockIdx.x * blockDim.x + threadIdx.x;
    if (e >= NEDGES) return;
    int d;
    if (g_idx64) d = (int)((const long long*)eiv)[NEDGES + e];
    else         d = ((const int*)eiv)[NEDGES + e];
    atomicAdd(&g_deg[d], 1);
}

// ---------------------------------------------------------------------------
// 3-kernel exclusive scan of g_deg -> g_off / g_cursor
__global__ void partial_kernel() {
    __shared__ int s[256];
    int i = blockIdx.x * 256 + threadIdx.x;
    int v = (i < NNODES) ? g_deg[i] : 0;
    s[threadIdx.x] = v; __syncthreads();
    for (int st = 128; st > 0; st >>= 1) {
        if (threadIdx.x < st) s[threadIdx.x] += s[threadIdx.x + st];
        __syncthreads();
    }
    if (threadIdx.x == 0) g_blocksum[blockIdx.x] = s[0];
}

__global__ void scanblock_kernel() {
    __shared__ int s[512];
    int t = threadIdx.x;
    int v = (t < NB) ? g_blocksum[t] : 0;
    s[t] = v; __syncthreads();
    for (int st = 1; st < 512; st <<= 1) {
        int add = (t >= st) ? s[t - st] : 0;
        __syncthreads();
        s[t] += add;
        __syncthreads();
    }
    if (t < NB) g_blockoff[t] = s[t] - v;   // exclusive
}

__global__ void offsets_kernel() {
    __shared__ int s[256];
    int i = blockIdx.x * 256 + threadIdx.x;
    int v = (i < NNODES) ? g_deg[i] : 0;
    s[threadIdx.x] = v; __syncthreads();
    for (int st = 1; st < 256; st <<= 1) {
        int add = (threadIdx.x >= st) ? s[threadIdx.x - st] : 0;
        __syncthreads();
        s[threadIdx.x] += add;
        __syncthreads();
    }
    int off = g_blockoff[blockIdx.x] + s[threadIdx.x] - v;  // exclusive
    if (i < NNODES) { g_off[i] = off; g_cursor[i] = off; }
    if (i == NNODES - 1) g_off[NNODES] = off + v;
}

__global__ void dis_kernel() {
    int i = blockIdx.x * blockDim.x + threadIdx.x;
    if (i >= NNODES) return;
    g_dis[i] = rsqrtf(fmaxf((float)g_deg[i], 1.0f));
}

// fill CSR: pos = cursor[dst]++ ; csr[pos] = {src, bits(dis[src])}
__global__ void fill_kernel(const void* __restrict__ eiv) {
    int e = blockIdx.x * blockDim.x + threadIdx.x;
    if (e >= NEDGES) return;
    int s, d;
    if (g_idx64) {
        const long long* p = (const long long*)eiv;
        s = (int)p[e]; d = (int)p[NEDGES + e];
    } else {
        const int* p = (const int*)eiv;
        s = p[e]; d = p[NEDGES + e];
    }
    int pos = atomicAdd(&g_cursor[d], 1);
    g_csr[pos] = make_int2(s, __float_as_int(g_dis[s]));
}

// ---------------------------------------------------------------------------
__global__ void init_kernel(const float4* __restrict__ x4) {
    int i = blockIdx.x * blockDim.x + threadIdx.x;
    if (i >= NF4) return;
    float4 v = x4[i];
    g_feat[0][2 * i]     = __floats2half2_rn(v.x, v.y);
    g_feat[0][2 * i + 1] = __floats2half2_rn(v.z, v.w);
}

// ---------------------------------------------------------------------------
// Warp-per-node gather, 4 edges per warp-iteration, 16 B per lane.
// Lane l: edge j + (l>>3), row segment (l&7). After the loop, the 4 edge
// groups are summed with 2 shfl_xor rounds; lanes 0..7 then hold the full
// 8-float segment sums for segments 0..7.
struct Acc8 { float4 lo, hi; };

__device__ __forceinline__ void gather_accum(int node, int lane,
                                             const uint4* __restrict__ fp,
                                             Acc8& A) {
    int beg = __ldg(&g_off[node]), end = __ldg(&g_off[node + 1]);
    int grp = lane >> 3;
    int sl  = lane & 7;

    float4 alo = {0.f, 0.f, 0.f, 0.f};
    float4 ahi = {0.f, 0.f, 0.f, 0.f};

    for (int j = beg; j < end; j += 4) {
        int e = j + grp;
        bool valid = (e < end);
        int idx = valid ? e : end - 1;
        int2 ed = __ldg(&g_csr[idx]);
        float w = valid ? __int_as_float(ed.y) : 0.f;

        uint4 r = __ldg(&fp[ed.x * 8 + sl]);
        float2 f0 = __half22float2(*reinterpret_cast<__half2*>(&r.x));
        float2 f1 = __half22float2(*reinterpret_cast<__half2*>(&r.y));
        float2 f2 = __half22float2(*reinterpret_cast<__half2*>(&r.z));
        float2 f3 = __half22float2(*reinterpret_cast<__half2*>(&r.w));

        alo.x = fmaf(w, f0.x, alo.x); alo.y = fmaf(w, f0.y, alo.y);
        alo.z = fmaf(w, f1.x, alo.z); alo.w = fmaf(w, f1.y, alo.w);
        ahi.x = fmaf(w, f2.x, ahi.x); ahi.y = fmaf(w, f2.y, ahi.y);
        ahi.z = fmaf(w, f3.x, ahi.z); ahi.w = fmaf(w, f3.y, ahi.w);
    }

    // Reduce across the 4 edge groups (lanes l, l^8, l^16, l^24).
#pragma unroll
    for (int m = 8; m <= 16; m <<= 1) {
        alo.x += __shfl_xor_sync(0xffffffffu, alo.x, m);
        alo.y += __shfl_xor_sync(0xffffffffu, alo.y, m);
        alo.z += __shfl_xor_sync(0xffffffffu, alo.z, m);
        alo.w += __shfl_xor_sync(0xffffffffu, alo.w, m);
        ahi.x += __shfl_xor_sync(0xffffffffu, ahi.x, m);
        ahi.y += __shfl_xor_sync(0xffffffffu, ahi.y, m);
        ahi.z += __shfl_xor_sync(0xffffffffu, ahi.z, m);
        ahi.w += __shfl_xor_sync(0xffffffffu, ahi.w, m);
    }
    A.lo = alo; A.hi = ahi;
}

// iterations k = 1..3: feat_k = feat_{k-1} - dis*agg  (fp16 store, lanes 0..7)
__global__ void gather_kernel(int k) {
    int t = blockIdx.x * blockDim.x + threadIdx.x;
    int node = t >> 5;
    if (node >= NNODES) return;
    int lane = t & 31;

    const uint4* fp = reinterpret_cast<const uint4*>(g_feat[k - 1]);
    uint4*       fn = reinterpret_cast<uint4*>(g_feat[k]);

    Acc8 A;
    gather_accum(node, lane, fp, A);

    if (lane < 8) {
        float disn = g_dis[node];
        uint4 own = fp[node * 8 + lane];
        float2 f0 = __half22float2(*reinterpret_cast<__half2*>(&own.x));
        float2 f1 = __half22float2(*reinterpret_cast<__half2*>(&own.y));
        float2 f2 = __half22float2(*reinterpret_cast<__half2*>(&own.z));
        float2 f3 = __half22float2(*reinterpret_cast<__half2*>(&own.w));

        __half2 o0 = __floats2half2_rn(f0.x - disn * A.lo.x, f0.y - disn * A.lo.y);
        __half2 o1 = __floats2half2_rn(f1.x - disn * A.lo.z, f1.y - disn * A.lo.w);
        __half2 o2 = __floats2half2_rn(f2.x - disn * A.hi.x, f2.y - disn * A.hi.y);
        __half2 o3 = __floats2half2_rn(f3.x - disn * A.hi.z, f3.y - disn * A.hi.w);

        uint4 out;
        out.x = *reinterpret_cast<unsigned*>(&o0);
        out.y = *reinterpret_cast<unsigned*>(&o1);
        out.z = *reinterpret_cast<unsigned*>(&o2);
        out.w = *reinterpret_cast<unsigned*>(&o3);
        fn[node * 8 + lane] = out;
    }
}

// iteration k = 4 fused with the polynomial combine:
// out = 0.6*x - 0.4*f1 + 0.3*f2 - 0.2*f3 + 0.1*(f3 - dis*agg)
__global__ void gather_final_kernel(const float4* __restrict__ x4,
                                    float4* __restrict__ out4) {
    int t = blockIdx.x * blockDim.x + threadIdx.x;
    int node = t >> 5;
    if (node >= NNODES) return;
    int lane = t & 31;

    const uint4* fp3 = reinterpret_cast<const uint4*>(g_feat[3]);

    Acc8 A;
    gather_accum(node, lane, fp3, A);

    if (lane < 8) {
        float disn = g_dis[node];
        int ri = node * 8 + lane;

        uint4 r3 = fp3[ri];
        uint4 r1 = reinterpret_cast<const uint4*>(g_feat[1])[ri];
        uint4 r2 = reinterpret_cast<const uint4*>(g_feat[2])[ri];

        float agg[8] = {A.lo.x, A.lo.y, A.lo.z, A.lo.w, A.hi.x, A.hi.y, A.hi.z, A.hi.w};
        unsigned w3[4] = {r3.x, r3.y, r3.z, r3.w};
        unsigned w1[4] = {r1.x, r1.y, r1.z, r1.w};
        unsigned w2[4] = {r2.x, r2.y, r2.z, r2.w};

        // x row: 64 floats; lane covers floats [lane*8, lane*8+8) = 2 float4
        float4 xv0 = __ldg(&x4[node * 16 + lane * 2]);
        float4 xv1 = __ldg(&x4[node * 16 + lane * 2 + 1]);
        float xs[8] = {xv0.x, xv0.y, xv0.z, xv0.w, xv1.x, xv1.y, xv1.z, xv1.w};

        float os[8];
#pragma unroll
        for (int q = 0; q < 4; q++) {
            float2 f3v = __half22float2(*reinterpret_cast<__half2*>(&w3[q]));
            float2 f1v = __half22float2(*reinterpret_cast<__half2*>(&w1[q]));
            float2 f2v = __half22float2(*reinterpret_cast<__half2*>(&w2[q]));
            float f4x = f3v.x - disn * agg[2 * q];
            float f4y = f3v.y - disn * agg[2 * q + 1];
            os[2 * q]     = fmaf(0.1f, f4x, fmaf(-0.2f, f3v.x,
                            fmaf(0.3f, f2v.x, fmaf(-0.4f, f1v.x, 0.6f * xs[2 * q]))));
            os[2 * q + 1] = fmaf(0.1f, f4y, fmaf(-0.2f, f3v.y,
                            fmaf(0.3f, f2v.y, fmaf(-0.4f, f1v.y, 0.6f * xs[2 * q + 1]))));
        }
        float4 o0 = {os[0], os[1], os[2], os[3]};
        float4 o1 = {os[4], os[5], os[6], os[7]};
        out4[node * 16 + lane * 2]     = o0;
        out4[node * 16 + lane * 2 + 1] = o1;
    }
}

// ---------------------------------------------------------------------------
extern "C" void kernel_launch(void* const* d_in, const int* in_sizes, int n_in,
                              void* d_out, int out_size) {
    const float4* x4 = (const float4*)d_in[0];
    const void*   ei = d_in[1];

    detect_idx_kernel<<<1, 32>>>((const int*)ei);
    zerodeg_kernel<<<NB, 256>>>();
    deg_kernel<<<(NEDGES + 255) / 256, 256>>>(ei);
    partial_kernel<<<NB, 256>>>();
    scanblock_kernel<<<1, 512>>>();
    offsets_kernel<<<NB, 256>>>();
    dis_kernel<<<NB, 256>>>();
    fill_kernel<<<(NEDGES + 255) / 256, 256>>>(ei);
    init_kernel<<<(NF4 + 255) / 256, 256>>>(x4);

    const int gthreads = NNODES * 32;
    const int gblocks = (gthreads + 255) / 256;
    for (int k = 1; k <= 3; k++)
        gather_kernel<<<gblocks, 256>>>(k);
    gather_final_kernel<<<gblocks, 256>>>(x4, (float4*)d_out);
}

// round 8
// speedup vs baseline: 1.2722x; 1.2072x over previous
#include <cuda_runtime.h>
#include <cuda_fp16.h>
#include <cstdint>

#define NNODES 100000
#define NEDGES 1600000
#define NB     391            // ceil(NNODES/256)
#define NF4    (NNODES * 16)  // float4 slots per fp32 plane (== NEDGES)

// ---------------------------------------------------------------------------
// Device-global scratch (no allocation allowed).
__device__ __half2 g_feat[4][NNODES * 32];   // planes 0..3 fp16, 12.8 MB each
__device__ int2    g_csr[NEDGES];            // {src, bits(dis[src])} sorted by dst
__device__ int     g_off[NNODES + 1];
__device__ int     g_cursor[NNODES];
__device__ int     g_deg[NNODES];
__device__ float   g_dis[NNODES];
__device__ int     g_blocksum[512];
__device__ int     g_blockoff[512];
__device__ int     g_idx64;

// ---------------------------------------------------------------------------
// detect index width (block 0 warp 0) + zero g_deg (all blocks)
__global__ void detect_zerodeg_kernel(const int* __restrict__ ei32) {
    int i = blockIdx.x * blockDim.x + threadIdx.x;
    if (i < NNODES) g_deg[i] = 0;
    if (blockIdx.x == 0 && threadIdx.x < 32) {
        int lane = threadIdx.x;
        int nz = 0;
        for (int q = lane; q < 2048; q += 32) nz |= ei32[2 * q + 1];
        unsigned m = __ballot_sync(0xffffffffu, nz != 0);
        if (lane == 0) g_idx64 = (m == 0) ? 1 : 0;
    }
}

// deg atomic (edge e) + feat0 init (float4 slot e) — both ranges are 1.6M
__global__ void deg_init_kernel(const void* __restrict__ eiv,
                                const float4* __restrict__ x4) {
    int e = blockIdx.x * blockDim.x + threadIdx.x;
    if (e >= NEDGES) return;
    int d;
    if (g_idx64) d = (int)((const long long*)eiv)[NEDGES + e];
    else         d = ((const int*)eiv)[NEDGES + e];
    atomicAdd(&g_deg[d], 1);

    float4 v = x4[e];
    g_feat[0][2 * e]     = __floats2half2_rn(v.x, v.y);
    g_feat[0][2 * e + 1] = __floats2half2_rn(v.z, v.w);
}

// ---------------------------------------------------------------------------
// 3-kernel exclusive scan of g_deg -> g_off / g_cursor (+ dis in pass 3)
__global__ void partial_kernel() {
    __shared__ int s[256];
    int i = blockIdx.x * 256 + threadIdx.x;
    int v = (i < NNODES) ? g_deg[i] : 0;
    s[threadIdx.x] = v; __syncthreads();
    for (int st = 128; st > 0; st >>= 1) {
        if (threadIdx.x < st) s[threadIdx.x] += s[threadIdx.x + st];
        __syncthreads();
    }
    if (threadIdx.x == 0) g_blocksum[blockIdx.x] = s[0];
}

__global__ void scanblock_kernel() {
    __shared__ int s[512];
    int t = threadIdx.x;
    int v = (t < NB) ? g_blocksum[t] : 0;
    s[t] = v; __syncthreads();
    for (int st = 1; st < 512; st <<= 1) {
        int add = (t >= st) ? s[t - st] : 0;
        __syncthreads();
        s[t] += add;
        __syncthreads();
    }
    if (t < NB) g_blockoff[t] = s[t] - v;   // exclusive
}

__global__ void offsets_dis_kernel() {
    __shared__ int s[256];
    int i = blockIdx.x * 256 + threadIdx.x;
    int v = (i < NNODES) ? g_deg[i] : 0;
    s[threadIdx.x] = v; __syncthreads();
    for (int st = 1; st < 256; st <<= 1) {
        int add = (threadIdx.x >= st) ? s[threadIdx.x - st] : 0;
        __syncthreads();
        s[threadIdx.x] += add;
        __syncthreads();
    }
    int off = g_blockoff[blockIdx.x] + s[threadIdx.x] - v;  // exclusive
    if (i < NNODES) {
        g_off[i] = off;
        g_cursor[i] = off;
        g_dis[i] = rsqrtf(fmaxf((float)v, 1.0f));
    }
    if (i == NNODES - 1) g_off[NNODES] = off + v;
}

// fill CSR: pos = cursor[dst]++ ; csr[pos] = {src, bits(dis[src])}
__global__ void fill_kernel(const void* __restrict__ eiv) {
    int e = blockIdx.x * blockDim.x + threadIdx.x;
    if (e >= NEDGES) return;
    int s, d;
    if (g_idx64) {
        const long long* p = (const long long*)eiv;
        s = (int)p[e]; d = (int)p[NEDGES + e];
    } else {
        const int* p = (const int*)eiv;
        s = p[e]; d = p[NEDGES + e];
    }
    int pos = atomicAdd(&g_cursor[d], 1);
    g_csr[pos] = make_int2(s, __float_as_int(g_dis[s]));
}

// ---------------------------------------------------------------------------
// R3-proven gather core: 8 lanes per node, lane owns 16 B (8 halves) of the
// row; per-thread 4-wide unroll gives MLP>=4 independent LDG.128s.
__device__ __forceinline__ void acc_row(float2& a0, float2& a1, float2& a2, float2& a3,
                                        float w, uint4 r) {
    float2 f0 = __half22float2(*reinterpret_cast<__half2*>(&r.x));
    float2 f1 = __half22float2(*reinterpret_cast<__half2*>(&r.y));
    float2 f2 = __half22float2(*reinterpret_cast<__half2*>(&r.z));
    float2 f3 = __half22float2(*reinterpret_cast<__half2*>(&r.w));
    a0.x = fmaf(w, f0.x, a0.x); a0.y = fmaf(w, f0.y, a0.y);
    a1.x = fmaf(w, f1.x, a1.x); a1.y = fmaf(w, f1.y, a1.y);
    a2.x = fmaf(w, f2.x, a2.x); a2.y = fmaf(w, f2.y, a2.y);
    a3.x = fmaf(w, f3.x, a3.x); a3.y = fmaf(w, f3.y, a3.y);
}

__device__ __forceinline__ void gather_accum(int node, int sl,
                                             const uint4* __restrict__ fp,
                                             float2& a0, float2& a1,
                                             float2& a2, float2& a3) {
    int beg = __ldg(&g_off[node]), end = __ldg(&g_off[node + 1]);
    a0 = {0.f, 0.f}; a1 = {0.f, 0.f}; a2 = {0.f, 0.f}; a3 = {0.f, 0.f};

    int j = beg;
    for (; j + 4 <= end; j += 4) {
        int2 e0 = __ldg(&g_csr[j]);
        int2 e1 = __ldg(&g_csr[j + 1]);
        int2 e2 = __ldg(&g_csr[j + 2]);
        int2 e3 = __ldg(&g_csr[j + 3]);
        uint4 r0 = __ldg(&fp[e0.x * 8 + sl]);
        uint4 r1 = __ldg(&fp[e1.x * 8 + sl]);
        uint4 r2 = __ldg(&fp[e2.x * 8 + sl]);
        uint4 r3 = __ldg(&fp[e3.x * 8 + sl]);
        acc_row(a0, a1, a2, a3, __int_as_float(e0.y), r0);
        acc_row(a0, a1, a2, a3, __int_as_float(e1.y), r1);
        acc_row(a0, a1, a2, a3, __int_as_float(e2.y), r2);
        acc_row(a0, a1, a2, a3, __int_as_float(e3.y), r3);
    }
    for (; j < end; j++) {
        int2 e0 = __ldg(&g_csr[j]);
        uint4 r0 = __ldg(&fp[e0.x * 8 + sl]);
        acc_row(a0, a1, a2, a3, __int_as_float(e0.y), r0);
    }
}

// iterations k = 1..3: feat_k = feat_{k-1} - dis*agg  (fp16 store)
__global__ void gather_kernel(int k) {
    int t = blockIdx.x * blockDim.x + threadIdx.x;
    int node = t >> 3;
    if (node >= NNODES) return;
    int sl = t & 7;

    const uint4* fp = reinterpret_cast<const uint4*>(g_feat[k - 1]);
    uint4*       fn = reinterpret_cast<uint4*>(g_feat[k]);

    float2 a0, a1, a2, a3;
    gather_accum(node, sl, fp, a0, a1, a2, a3);

    float disn = g_dis[node];
    uint4 own = fp[node * 8 + sl];
    float2 f0 = __half22float2(*reinterpret_cast<__half2*>(&own.x));
    float2 f1 = __half22float2(*reinterpret_cast<__half2*>(&own.y));
    float2 f2 = __half22float2(*reinterpret_cast<__half2*>(&own.z));
    float2 f3 = __half22float2(*reinterpret_cast<__half2*>(&own.w));

    __half2 o0 = __floats2half2_rn(f0.x - disn * a0.x, f0.y - disn * a0.y);
    __half2 o1 = __floats2half2_rn(f1.x - disn * a1.x, f1.y - disn * a1.y);
    __half2 o2 = __floats2half2_rn(f2.x - disn * a2.x, f2.y - disn * a2.y);
    __half2 o3 = __floats2half2_rn(f3.x - disn * a3.x, f3.y - disn * a3.y);

    uint4 out;
    out.x = *reinterpret_cast<unsigned*>(&o0);
    out.y = *reinterpret_cast<unsigned*>(&o1);
    out.z = *reinterpret_cast<unsigned*>(&o2);
    out.w = *reinterpret_cast<unsigned*>(&o3);
    fn[node * 8 + sl] = out;
}

// iteration k = 4 fused with the polynomial combine:
// out = 0.6*x - 0.4*f1 + 0.3*f2 - 0.2*f3 + 0.1*(f3 - dis*agg)
__global__ void gather_final_kernel(const float4* __restrict__ x4,
                                    float4* __restrict__ out4) {
    int t = blockIdx.x * blockDim.x + threadIdx.x;
    int node = t >> 3;
    if (node >= NNODES) return;
    int sl = t & 7;

    const uint4* fp3 = reinterpret_cast<const uint4*>(g_feat[3]);

    float2 a0, a1, a2, a3;
    gather_accum(node, sl, fp3, a0, a1, a2, a3);

    float disn = g_dis[node];
    int ri = node * 8 + sl;

    uint4 r3 = fp3[ri];
    uint4 r1 = reinterpret_cast<const uint4*>(g_feat[1])[ri];
    uint4 r2 = reinterpret_cast<const uint4*>(g_feat[2])[ri];

    float agg[8] = {a0.x, a0.y, a1.x, a1.y, a2.x, a2.y, a3.x, a3.y};
    unsigned w3[4] = {r3.x, r3.y, r3.z, r3.w};
    unsigned w1[4] = {r1.x, r1.y, r1.z, r1.w};
    unsigned w2[4] = {r2.x, r2.y, r2.z, r2.w};

    // x row: lane covers floats [sl*8, sl*8+8) = 2 float4
    float4 xv0 = __ldg(&x4[node * 16 + sl * 2]);
    float4 xv1 = __ldg(&x4[node * 16 + sl * 2 + 1]);
    float xs[8] = {xv0.x, xv0.y, xv0.z, xv0.w, xv1.x, xv1.y, xv1.z, xv1.w};

    float os[8];
#pragma unroll
    for (int q = 0; q < 4; q++) {
        float2 f3v = __half22float2(*reinterpret_cast<__half2*>(&w3[q]));
        float2 f1v = __half22float2(*reinterpret_cast<__half2*>(&w1[q]));
        float2 f2v = __half22float2(*reinterpret_cast<__half2*>(&w2[q]));
        float f4x = f3v.x - disn * agg[2 * q];
        float f4y = f3v.y - disn * agg[2 * q + 1];
        os[2 * q]     = fmaf(0.1f, f4x, fmaf(-0.2f, f3v.x,
                        fmaf(0.3f, f2v.x, fmaf(-0.4f, f1v.x, 0.6f * xs[2 * q]))));
        os[2 * q + 1] = fmaf(0.1f, f4y, fmaf(-0.2f, f3v.y,
                        fmaf(0.3f, f2v.y, fmaf(-0.4f, f1v.y, 0.6f * xs[2 * q + 1]))));
    }
    float4 o0 = {os[0], os[1], os[2], os[3]};
    float4 o1 = {os[4], os[5], os[6], os[7]};
    out4[node * 16 + sl * 2]     = o0;
    out4[node * 16 + sl * 2 + 1] = o1;
}

// ---------------------------------------------------------------------------
extern "C" void kernel_launch(void* const* d_in, const int* in_sizes, int n_in,
                              void* d_out, int out_size) {
    const float4* x4 = (const float4*)d_in[0];
    const void*   ei = d_in[1];

    detect_zerodeg_kernel<<<NB, 256>>>((const int*)ei);
    deg_init_kernel<<<(NEDGES + 255) / 256, 256>>>(ei, x4);
    partial_kernel<<<NB, 256>>>();
    scanblock_kernel<<<1, 512>>>();
    offsets_dis_kernel<<<NB, 256>>>();
    fill_kernel<<<(NEDGES + 255) / 256, 256>>>(ei);

    const int gthreads = NNODES * 8;
    const int gblocks = (gthreads + 255) / 256;
    for (int k = 1; k <= 3; k++)
        gather_kernel<<<gblocks, 256>>>(k);
    gather_final_kernel<<<gblocks, 256>>>(x4, (float4*)d_out);
}